// round 3
// baseline (speedup 1.0000x reference)
#include <cuda_runtime.h>
#include <math_constants.h>

#define B_   4
#define T_   4096
#define EMB_ 768
#define HS_  64
#define BT_  (B_*T_)

// Scratch for projected K/Q/V (4 MB each) — __device__ globals (no allocs allowed).
__device__ float g_K[BT_*HS_];
__device__ float g_Q[BT_*HS_];
__device__ float g_V[BT_*HS_];

// ---------------------------------------------------------------------------
// Projection: k/q/v = x @ W + b, fused (x read once).
// Block = 32 rows, 256 threads = 64 cols x 4 row-groups; each thread: 8 rows,
// 1 col, 3 matrices -> 24 fp32 accumulators. x tiles staged in smem, W via L1.
// ---------------------------------------------------------------------------
__global__ __launch_bounds__(256) void proj_kernel(
    const float* __restrict__ x,
    const float* __restrict__ Wk, const float* __restrict__ bk,
    const float* __restrict__ Wq, const float* __restrict__ bq,
    const float* __restrict__ Wv, const float* __restrict__ bv)
{
    __shared__ float sx[32][64];
    const int row0 = blockIdx.x * 32;
    const int c  = threadIdx.x & 63;   // output column 0..63
    const int rg = threadIdx.x >> 6;   // row group 0..3 (8 rows each)

    float ak[8], aq[8], av[8];
#pragma unroll
    for (int i = 0; i < 8; ++i) { ak[i] = 0.f; aq[i] = 0.f; av[i] = 0.f; }

    for (int e0 = 0; e0 < EMB_; e0 += 64) {
        __syncthreads();
        // 32x64 fp32 tile = 512 float4, 2 per thread, coalesced
#pragma unroll
        for (int i = threadIdx.x; i < 512; i += 256) {
            int r = i >> 4, cc = i & 15;
            ((float4*)sx[r])[cc] =
                ((const float4*)(x + (size_t)(row0 + r) * EMB_ + e0))[cc];
        }
        __syncthreads();

#pragma unroll 4
        for (int e = 0; e < 64; e += 4) {
            const float* wkp = Wk + (size_t)(e0 + e) * HS_ + c;
            const float* wqp = Wq + (size_t)(e0 + e) * HS_ + c;
            const float* wvp = Wv + (size_t)(e0 + e) * HS_ + c;
            float wk0 = wkp[0], wk1 = wkp[HS_], wk2 = wkp[2*HS_], wk3 = wkp[3*HS_];
            float wq0 = wqp[0], wq1 = wqp[HS_], wq2 = wqp[2*HS_], wq3 = wqp[3*HS_];
            float wv0 = wvp[0], wv1 = wvp[HS_], wv2 = wvp[2*HS_], wv3 = wvp[3*HS_];
#pragma unroll
            for (int i = 0; i < 8; ++i) {
                float4 xv = *(const float4*)(&sx[rg*8 + i][e]);   // broadcast LDS
                ak[i] += xv.x*wk0; ak[i] += xv.y*wk1; ak[i] += xv.z*wk2; ak[i] += xv.w*wk3;
                aq[i] += xv.x*wq0; aq[i] += xv.y*wq1; aq[i] += xv.z*wq2; aq[i] += xv.w*wq3;
                av[i] += xv.x*wv0; av[i] += xv.y*wv1; av[i] += xv.z*wv2; av[i] += xv.w*wv3;
            }
        }
    }

    const float bkv = bk[c], bqv = bq[c], bvv = bv[c];
#pragma unroll
    for (int i = 0; i < 8; ++i) {
        int row = row0 + rg*8 + i;
        g_K[(size_t)row*HS_ + c] = ak[i] + bkv;
        g_Q[(size_t)row*HS_ + c] = aq[i] + bqv;
        g_V[(size_t)row*HS_ + c] = av[i] + bvv;
    }
}

// ---------------------------------------------------------------------------
// Flash attention, fp32. Roles per reference: "query" = K-proj rows (t),
// "key" = Q-proj rows (s), value = V. Causal: s <= t. No scaling.
//
// Block: 256 threads as 16x16; thread computes rows ty*4..+3, cols tx+16j
// (4x4 register tile of S and of O). 64x64 tiles. Tile pairing (p, 63-p)
// equalizes causal work: every block does exactly 65 inner iterations.
// Smem: sA (plain) + sBP (sB swizzled, reused as P plain) + sVt (swizzled
// transposed V) = 48 KB static exactly. XOR-granule swizzle keeps LDS.128
// conflict-free without padding.
// ---------------------------------------------------------------------------
__global__ __launch_bounds__(256) void attn_kernel(float* __restrict__ out)
{
    __shared__ float sA [64*64];   // k-proj tile (row-major, broadcast reads)
    __shared__ float sBP[64*64];   // q-proj tile (swizzled) then P (plain)
    __shared__ float sVt[64*64];   // V transposed [h][s] (swizzled)

    const int b  = blockIdx.y;
    const int tx = threadIdx.x & 15;
    const int ty = threadIdx.x >> 4;

    const float* Kb = g_K + (size_t)b * T_ * HS_;
    const float* Qb = g_Q + (size_t)b * T_ * HS_;
    const float* Vb = g_V + (size_t)b * T_ * HS_;

    for (int pass = 0; pass < 2; ++pass) {
        const int ti = (pass == 0) ? (int)blockIdx.x : 63 - (int)blockIdx.x;
        const int t0 = ti * 64;

        __syncthreads();   // previous pass fully done with smem
        // load sA: 64x64 = 1024 float4, 4 per thread
#pragma unroll
        for (int i = threadIdx.x; i < 1024; i += 256) {
            int r = i >> 4, cc = i & 15;
            ((float4*)(sA + r*64))[cc] =
                ((const float4*)(Kb + (size_t)(t0 + r) * HS_))[cc];
        }

        float m_i[4], l_i[4], acc[4][4];
#pragma unroll
        for (int i = 0; i < 4; ++i) {
            m_i[i] = -CUDART_INF_F; l_i[i] = 0.f;
#pragma unroll
            for (int j = 0; j < 4; ++j) acc[i][j] = 0.f;
        }

        for (int s0 = 0; s0 <= t0; s0 += 64) {
            __syncthreads();   // prev iter done with sBP(P) & sVt; sA visible
            // load sB (swizzled) and sVt (transposed, swizzled)
#pragma unroll
            for (int i = threadIdx.x; i < 1024; i += 256) {
                int r = i >> 4, cc = i & 15;
                float4 qv = *(const float4*)(Qb + (size_t)(s0 + r) * HS_ + cc*4);
                *(float4*)(sBP + r*64 + ((cc ^ (r & 15)) << 2)) = qv;
                float4 vv = *(const float4*)(Vb + (size_t)(s0 + r) * HS_ + cc*4);
                int g = r >> 2, rb = r & 3, h0 = cc*4;
                sVt[(h0+0)*64 + ((g ^ ((h0+0) & 15)) << 2) + rb] = vv.x;
                sVt[(h0+1)*64 + ((g ^ ((h0+1) & 15)) << 2) + rb] = vv.y;
                sVt[(h0+2)*64 + ((g ^ ((h0+2) & 15)) << 2) + rb] = vv.z;
                sVt[(h0+3)*64 + ((g ^ ((h0+3) & 15)) << 2) + rb] = vv.w;
            }
            __syncthreads();

            // GEMM1: S[i][j] = sum_h sA[ty*4+i][h] * sB[tx+16j][h]
            float S[4][4];
#pragma unroll
            for (int i = 0; i < 4; ++i)
#pragma unroll
                for (int j = 0; j < 4; ++j) S[i][j] = 0.f;

#pragma unroll
            for (int h = 0; h < 64; h += 4) {
                float4 a[4], qq[4];
#pragma unroll
                for (int i = 0; i < 4; ++i)
                    a[i] = *(const float4*)(sA + (ty*4 + i)*64 + h);
#pragma unroll
                for (int j = 0; j < 4; ++j) {
                    int R = tx + 16*j;
                    qq[j] = *(const float4*)(sBP + R*64 + (((h >> 2) ^ (R & 15)) << 2));
                }
#pragma unroll
                for (int i = 0; i < 4; ++i)
#pragma unroll
                    for (int j = 0; j < 4; ++j)
                        S[i][j] += a[i].x*qq[j].x + a[i].y*qq[j].y
                                 + a[i].z*qq[j].z + a[i].w*qq[j].w;
            }

            // causal mask (only the diagonal tile needs it)
            if (s0 == t0) {
#pragma unroll
                for (int i = 0; i < 4; ++i)
#pragma unroll
                    for (int j = 0; j < 4; ++j)
                        if (tx + 16*j > ty*4 + i) S[i][j] = -CUDART_INF_F;
            }

            __syncthreads();   // all GEMM1 reads of sBP done before P overwrite

            // online softmax; write P (plain layout) into sBP
#pragma unroll
            for (int i = 0; i < 4; ++i) {
                float rmax = fmaxf(fmaxf(S[i][0], S[i][1]), fmaxf(S[i][2], S[i][3]));
#pragma unroll
                for (int k = 8; k >= 1; k >>= 1)
                    rmax = fmaxf(rmax, __shfl_xor_sync(0xffffffffu, rmax, k, 16));
                float mnew = fmaxf(m_i[i], rmax);
                float corr = __expf(m_i[i] - mnew);
                m_i[i] = mnew;
                float rsum = 0.f;
#pragma unroll
                for (int j = 0; j < 4; ++j) {
                    S[i][j] = __expf(S[i][j] - mnew);
                    rsum += S[i][j];
                }
#pragma unroll
                for (int k = 8; k >= 1; k >>= 1)
                    rsum += __shfl_xor_sync(0xffffffffu, rsum, k, 16);
                l_i[i] = l_i[i]*corr + rsum;
#pragma unroll
                for (int j = 0; j < 4; ++j) {
                    acc[i][j] *= corr;
                    sBP[(ty*4 + i)*64 + tx + 16*j] = S[i][j];
                }
            }
            __syncthreads();   // P visible

            // GEMM2: acc[i][j] += sum_s P[ty*4+i][s] * Vt[tx+16j][s]
#pragma unroll
            for (int s = 0; s < 64; s += 4) {
                float4 p4[4], v4[4];
#pragma unroll
                for (int i = 0; i < 4; ++i)
                    p4[i] = *(const float4*)(sBP + (ty*4 + i)*64 + s);
#pragma unroll
                for (int j = 0; j < 4; ++j) {
                    int H = tx + 16*j;
                    v4[j] = *(const float4*)(sVt + H*64 + (((s >> 2) ^ (H & 15)) << 2));
                }
#pragma unroll
                for (int i = 0; i < 4; ++i)
#pragma unroll
                    for (int j = 0; j < 4; ++j)
                        acc[i][j] += p4[i].x*v4[j].x + p4[i].y*v4[j].y
                                   + p4[i].z*v4[j].z + p4[i].w*v4[j].w;
            }
        }

        // epilogue: O = acc / l
#pragma unroll
        for (int i = 0; i < 4; ++i) {
            float inv = 1.f / l_i[i];
            int t = t0 + ty*4 + i;
            float* op = out + ((size_t)b * T_ + t) * HS_;
#pragma unroll
            for (int j = 0; j < 4; ++j)
                op[tx + 16*j] = acc[i][j] * inv;
        }
    }
}

// ---------------------------------------------------------------------------
extern "C" void kernel_launch(void* const* d_in, const int* in_sizes, int n_in,
                              void* d_out, int out_size)
{
    (void)in_sizes; (void)n_in; (void)out_size;
    const float* x  = (const float*)d_in[0];
    const float* Wk = (const float*)d_in[1];
    const float* bk = (const float*)d_in[2];
    const float* Wq = (const float*)d_in[3];
    const float* bq = (const float*)d_in[4];
    const float* Wv = (const float*)d_in[5];
    const float* bv = (const float*)d_in[6];
    float* out = (float*)d_out;

    proj_kernel<<<BT_/32, 256>>>(x, Wk, bk, Wq, bq, Wv, bv);
    attn_kernel<<<dim3(32, B_), 256>>>(out);
}

// round 4
// speedup vs baseline: 1.0044x; 1.0044x over previous
#include <cuda_runtime.h>
#include <math_constants.h>

#define B_   4
#define T_   4096
#define EMB_ 768
#define HS_  64
#define BT_  (B_*T_)

// Scratch for projected K/Q/V (4 MB each) — __device__ globals (no allocs allowed).
__device__ float g_K[BT_*HS_];
__device__ float g_Q[BT_*HS_];
__device__ float g_V[BT_*HS_];

// ---------------------------------------------------------------------------
// Projection: k/q/v = x @ W + b, fused (x read once).
// Block = 32 rows, 256 threads = 64 cols x 4 row-groups; each thread: 8 rows,
// 1 col, 3 matrices -> 24 fp32 accumulators. x tiles staged in smem, W via L1.
// ---------------------------------------------------------------------------
__global__ __launch_bounds__(256) void proj_kernel(
    const float* __restrict__ x,
    const float* __restrict__ Wk, const float* __restrict__ bk,
    const float* __restrict__ Wq, const float* __restrict__ bq,
    const float* __restrict__ Wv, const float* __restrict__ bv)
{
    __shared__ float sx[32][64];
    const int row0 = blockIdx.x * 32;
    const int c  = threadIdx.x & 63;   // output column 0..63
    const int rg = threadIdx.x >> 6;   // row group 0..3 (8 rows each)

    float ak[8], aq[8], av[8];
#pragma unroll
    for (int i = 0; i < 8; ++i) { ak[i] = 0.f; aq[i] = 0.f; av[i] = 0.f; }

    for (int e0 = 0; e0 < EMB_; e0 += 64) {
        __syncthreads();
        // 32x64 fp32 tile = 512 float4, 2 per thread, coalesced
#pragma unroll
        for (int i = threadIdx.x; i < 512; i += 256) {
            int r = i >> 4, cc = i & 15;
            ((float4*)sx[r])[cc] =
                ((const float4*)(x + (size_t)(row0 + r) * EMB_ + e0))[cc];
        }
        __syncthreads();

#pragma unroll 4
        for (int e = 0; e < 64; e += 4) {
            const float* wkp = Wk + (size_t)(e0 + e) * HS_ + c;
            const float* wqp = Wq + (size_t)(e0 + e) * HS_ + c;
            const float* wvp = Wv + (size_t)(e0 + e) * HS_ + c;
            float wk0 = wkp[0], wk1 = wkp[HS_], wk2 = wkp[2*HS_], wk3 = wkp[3*HS_];
            float wq0 = wqp[0], wq1 = wqp[HS_], wq2 = wqp[2*HS_], wq3 = wqp[3*HS_];
            float wv0 = wvp[0], wv1 = wvp[HS_], wv2 = wvp[2*HS_], wv3 = wvp[3*HS_];
#pragma unroll
            for (int i = 0; i < 8; ++i) {
                float4 xv = *(const float4*)(&sx[rg*8 + i][e]);   // broadcast LDS
                ak[i] += xv.x*wk0; ak[i] += xv.y*wk1; ak[i] += xv.z*wk2; ak[i] += xv.w*wk3;
                aq[i] += xv.x*wq0; aq[i] += xv.y*wq1; aq[i] += xv.z*wq2; aq[i] += xv.w*wq3;
                av[i] += xv.x*wv0; av[i] += xv.y*wv1; av[i] += xv.z*wv2; av[i] += xv.w*wv3;
            }
        }
    }

    const float bkv = bk[c], bqv = bq[c], bvv = bv[c];
#pragma unroll
    for (int i = 0; i < 8; ++i) {
        int row = row0 + rg*8 + i;
        g_K[(size_t)row*HS_ + c] = ak[i] + bkv;
        g_Q[(size_t)row*HS_ + c] = aq[i] + bqv;
        g_V[(size_t)row*HS_ + c] = av[i] + bvv;
    }
}

// ---------------------------------------------------------------------------
// Flash attention, fp32. Roles per reference: "query" = K-proj rows (t),
// "key" = Q-proj rows (s), value = V. Causal: s <= t. No scaling.
//
// Block: 256 threads as 16x16; thread computes rows ty*4..+3, cols tx+16j
// (4x4 register tile of S and of O). 64x64 tiles. Tile pairing (p, 63-p)
// equalizes causal work: every block does exactly 65 inner iterations.
// Smem: sA (plain) + sBP (sB swizzled, reused as P plain) + sVt (swizzled
// transposed V) = 48 KB static exactly. XOR-granule swizzle keeps LDS.128
// conflict-free without padding.
// ---------------------------------------------------------------------------
__global__ __launch_bounds__(256) void attn_kernel(float* __restrict__ out)
{
    __shared__ float sA [64*64];   // k-proj tile (row-major, broadcast reads)
    __shared__ float sBP[64*64];   // q-proj tile (swizzled) then P (plain)
    __shared__ float sVt[64*64];   // V transposed [h][s] (swizzled)

    const int b  = blockIdx.y;
    const int tx = threadIdx.x & 15;
    const int ty = threadIdx.x >> 4;

    const float* Kb = g_K + (size_t)b * T_ * HS_;
    const float* Qb = g_Q + (size_t)b * T_ * HS_;
    const float* Vb = g_V + (size_t)b * T_ * HS_;

    for (int pass = 0; pass < 2; ++pass) {
        const int ti = (pass == 0) ? (int)blockIdx.x : 63 - (int)blockIdx.x;
        const int t0 = ti * 64;

        __syncthreads();   // previous pass fully done with smem
        // load sA: 64x64 = 1024 float4, 4 per thread
#pragma unroll
        for (int i = threadIdx.x; i < 1024; i += 256) {
            int r = i >> 4, cc = i & 15;
            ((float4*)(sA + r*64))[cc] =
                ((const float4*)(Kb + (size_t)(t0 + r) * HS_))[cc];
        }

        float m_i[4], l_i[4], acc[4][4];
#pragma unroll
        for (int i = 0; i < 4; ++i) {
            m_i[i] = -CUDART_INF_F; l_i[i] = 0.f;
#pragma unroll
            for (int j = 0; j < 4; ++j) acc[i][j] = 0.f;
        }

        for (int s0 = 0; s0 <= t0; s0 += 64) {
            __syncthreads();   // prev iter done with sBP(P) & sVt; sA visible
            // load sB (swizzled) and sVt (transposed, swizzled)
#pragma unroll
            for (int i = threadIdx.x; i < 1024; i += 256) {
                int r = i >> 4, cc = i & 15;
                float4 qv = *(const float4*)(Qb + (size_t)(s0 + r) * HS_ + cc*4);
                *(float4*)(sBP + r*64 + ((cc ^ (r & 15)) << 2)) = qv;
                float4 vv = *(const float4*)(Vb + (size_t)(s0 + r) * HS_ + cc*4);
                int g = r >> 2, rb = r & 3, h0 = cc*4;
                sVt[(h0+0)*64 + ((g ^ ((h0+0) & 15)) << 2) + rb] = vv.x;
                sVt[(h0+1)*64 + ((g ^ ((h0+1) & 15)) << 2) + rb] = vv.y;
                sVt[(h0+2)*64 + ((g ^ ((h0+2) & 15)) << 2) + rb] = vv.z;
                sVt[(h0+3)*64 + ((g ^ ((h0+3) & 15)) << 2) + rb] = vv.w;
            }
            __syncthreads();

            // GEMM1: S[i][j] = sum_h sA[ty*4+i][h] * sB[tx+16j][h]
            float S[4][4];
#pragma unroll
            for (int i = 0; i < 4; ++i)
#pragma unroll
                for (int j = 0; j < 4; ++j) S[i][j] = 0.f;

#pragma unroll
            for (int h = 0; h < 64; h += 4) {
                float4 a[4], qq[4];
#pragma unroll
                for (int i = 0; i < 4; ++i)
                    a[i] = *(const float4*)(sA + (ty*4 + i)*64 + h);
#pragma unroll
                for (int j = 0; j < 4; ++j) {
                    int R = tx + 16*j;
                    qq[j] = *(const float4*)(sBP + R*64 + (((h >> 2) ^ (R & 15)) << 2));
                }
#pragma unroll
                for (int i = 0; i < 4; ++i)
#pragma unroll
                    for (int j = 0; j < 4; ++j)
                        S[i][j] += a[i].x*qq[j].x + a[i].y*qq[j].y
                                 + a[i].z*qq[j].z + a[i].w*qq[j].w;
            }

            // causal mask (only the diagonal tile needs it)
            if (s0 == t0) {
#pragma unroll
                for (int i = 0; i < 4; ++i)
#pragma unroll
                    for (int j = 0; j < 4; ++j)
                        if (tx + 16*j > ty*4 + i) S[i][j] = -CUDART_INF_F;
            }

            __syncthreads();   // all GEMM1 reads of sBP done before P overwrite

            // online softmax; write P (plain layout) into sBP
#pragma unroll
            for (int i = 0; i < 4; ++i) {
                float rmax = fmaxf(fmaxf(S[i][0], S[i][1]), fmaxf(S[i][2], S[i][3]));
#pragma unroll
                for (int k = 8; k >= 1; k >>= 1)
                    rmax = fmaxf(rmax, __shfl_xor_sync(0xffffffffu, rmax, k, 16));
                float mnew = fmaxf(m_i[i], rmax);
                float corr = __expf(m_i[i] - mnew);
                m_i[i] = mnew;
                float rsum = 0.f;
#pragma unroll
                for (int j = 0; j < 4; ++j) {
                    S[i][j] = __expf(S[i][j] - mnew);
                    rsum += S[i][j];
                }
#pragma unroll
                for (int k = 8; k >= 1; k >>= 1)
                    rsum += __shfl_xor_sync(0xffffffffu, rsum, k, 16);
                l_i[i] = l_i[i]*corr + rsum;
#pragma unroll
                for (int j = 0; j < 4; ++j) {
                    acc[i][j] *= corr;
                    sBP[(ty*4 + i)*64 + tx + 16*j] = S[i][j];
                }
            }
            __syncthreads();   // P visible

            // GEMM2: acc[i][j] += sum_s P[ty*4+i][s] * Vt[tx+16j][s]
#pragma unroll
            for (int s = 0; s < 64; s += 4) {
                float4 p4[4], v4[4];
#pragma unroll
                for (int i = 0; i < 4; ++i)
                    p4[i] = *(const float4*)(sBP + (ty*4 + i)*64 + s);
#pragma unroll
                for (int j = 0; j < 4; ++j) {
                    int H = tx + 16*j;
                    v4[j] = *(const float4*)(sVt + H*64 + (((s >> 2) ^ (H & 15)) << 2));
                }
#pragma unroll
                for (int i = 0; i < 4; ++i)
#pragma unroll
                    for (int j = 0; j < 4; ++j)
                        acc[i][j] += p4[i].x*v4[j].x + p4[i].y*v4[j].y
                                   + p4[i].z*v4[j].z + p4[i].w*v4[j].w;
            }
        }

        // epilogue: O = acc / l
#pragma unroll
        for (int i = 0; i < 4; ++i) {
            float inv = 1.f / l_i[i];
            int t = t0 + ty*4 + i;
            float* op = out + ((size_t)b * T_ + t) * HS_;
#pragma unroll
            for (int j = 0; j < 4; ++j)
                op[tx + 16*j] = acc[i][j] * inv;
        }
    }
}

// ---------------------------------------------------------------------------
extern "C" void kernel_launch(void* const* d_in, const int* in_sizes, int n_in,
                              void* d_out, int out_size)
{
    (void)in_sizes; (void)n_in; (void)out_size;
    const float* x  = (const float*)d_in[0];
    const float* Wk = (const float*)d_in[1];
    const float* bk = (const float*)d_in[2];
    const float* Wq = (const float*)d_in[3];
    const float* bq = (const float*)d_in[4];
    const float* Wv = (const float*)d_in[5];
    const float* bv = (const float*)d_in[6];
    float* out = (float*)d_out;

    proj_kernel<<<BT_/32, 256>>>(x, Wk, bk, Wq, bq, Wv, bv);
    attn_kernel<<<dim3(32, B_), 256>>>(out);
}

// round 7
// speedup vs baseline: 1.1569x; 1.1518x over previous
#include <cuda_runtime.h>
#include <cuda_bf16.h>
#include <cstdint>
#include <math_constants.h>

#define B_   4
#define T_   4096
#define EMB_ 768
#define HS_  64
#define BT_  (B_*T_)

// bf16 split operands produced by proj, consumed by attention MMAs.
__device__ __nv_bfloat16 g_Khi[BT_*HS_];
__device__ __nv_bfloat16 g_Klo[BT_*HS_];
__device__ __nv_bfloat16 g_Qhi[BT_*HS_];
__device__ __nv_bfloat16 g_Qlo[BT_*HS_];
__device__ __nv_bfloat16 g_Vthi[B_*HS_*T_];   // [b][h][t]
__device__ __nv_bfloat16 g_Vtlo[B_*HS_*T_];

__device__ __forceinline__ uint32_t smem_u32(const void* p) {
    uint32_t a;
    asm("{ .reg .u64 t; cvta.to.shared.u64 t, %1; cvt.u32.u64 %0, t; }"
        : "=r"(a) : "l"(p));
    return a;
}
__device__ __forceinline__ void ldsm_x4(uint32_t* r, uint32_t addr) {
    asm volatile("ldmatrix.sync.aligned.m8n8.x4.shared.b16 {%0,%1,%2,%3}, [%4];"
        : "=r"(r[0]), "=r"(r[1]), "=r"(r[2]), "=r"(r[3]) : "r"(addr));
}
__device__ __forceinline__ void mma16816(float* d, const uint32_t* a, const uint32_t* b) {
    asm volatile("mma.sync.aligned.m16n8k16.row.col.f32.bf16.bf16.f32 "
        "{%0,%1,%2,%3},{%4,%5,%6,%7},{%8,%9},{%0,%1,%2,%3};"
        : "+f"(d[0]), "+f"(d[1]), "+f"(d[2]), "+f"(d[3])
        : "r"(a[0]), "r"(a[1]), "r"(a[2]), "r"(a[3]), "r"(b[0]), "r"(b[1]));
}

// ===========================================================================
// Projection (SIMT fp32, known-good math). Epilogue emits bf16 hi/lo splits;
// V written transposed [b][h][t].
// ===========================================================================
__global__ __launch_bounds__(256) void proj_kernel(
    const float* __restrict__ x,
    const float* __restrict__ Wk, const float* __restrict__ bk,
    const float* __restrict__ Wq, const float* __restrict__ bq,
    const float* __restrict__ Wv, const float* __restrict__ bv)
{
    __shared__ float sx[32][64];
    const int row0 = blockIdx.x * 32;
    const int c  = threadIdx.x & 63;
    const int rg = threadIdx.x >> 6;

    float ak[8], aq[8], av[8];
#pragma unroll
    for (int i = 0; i < 8; ++i) { ak[i] = 0.f; aq[i] = 0.f; av[i] = 0.f; }

    for (int e0 = 0; e0 < EMB_; e0 += 64) {
        __syncthreads();
#pragma unroll
        for (int i = threadIdx.x; i < 512; i += 256) {
            int r = i >> 4, cc = i & 15;
            ((float4*)sx[r])[cc] =
                ((const float4*)(x + (size_t)(row0 + r) * EMB_ + e0))[cc];
        }
        __syncthreads();
#pragma unroll 4
        for (int e = 0; e < 64; e += 4) {
            const float* wkp = Wk + (size_t)(e0 + e) * HS_ + c;
            const float* wqp = Wq + (size_t)(e0 + e) * HS_ + c;
            const float* wvp = Wv + (size_t)(e0 + e) * HS_ + c;
            float wk0 = wkp[0], wk1 = wkp[HS_], wk2 = wkp[2*HS_], wk3 = wkp[3*HS_];
            float wq0 = wqp[0], wq1 = wqp[HS_], wq2 = wqp[2*HS_], wq3 = wqp[3*HS_];
            float wv0 = wvp[0], wv1 = wvp[HS_], wv2 = wvp[2*HS_], wv3 = wvp[3*HS_];
#pragma unroll
            for (int i = 0; i < 8; ++i) {
                float4 xv = *(const float4*)(&sx[rg*8 + i][e]);
                ak[i] += xv.x*wk0; ak[i] += xv.y*wk1; ak[i] += xv.z*wk2; ak[i] += xv.w*wk3;
                aq[i] += xv.x*wq0; aq[i] += xv.y*wq1; aq[i] += xv.z*wq2; aq[i] += xv.w*wq3;
                av[i] += xv.x*wv0; av[i] += xv.y*wv1; av[i] += xv.z*wv2; av[i] += xv.w*wv3;
            }
        }
    }

    const float bkv = bk[c], bqv = bq[c], bvv = bv[c];
#pragma unroll
    for (int i = 0; i < 8; ++i) {
        int row = row0 + rg*8 + i;
        float kv = ak[i] + bkv, qv = aq[i] + bqv, vv = av[i] + bvv;
        __nv_bfloat16 kh = __float2bfloat16(kv);
        __nv_bfloat16 qh = __float2bfloat16(qv);
        __nv_bfloat16 vh = __float2bfloat16(vv);
        g_Khi[(size_t)row*HS_ + c] = kh;
        g_Klo[(size_t)row*HS_ + c] = __float2bfloat16(kv - __bfloat162float(kh));
        g_Qhi[(size_t)row*HS_ + c] = qh;
        g_Qlo[(size_t)row*HS_ + c] = __float2bfloat16(qv - __bfloat162float(qh));
        int bb = row >> 12, t = row & (T_ - 1);
        size_t vo = ((size_t)bb * HS_ + c) * T_ + t;
        g_Vthi[vo] = vh;
        g_Vtlo[vo] = __float2bfloat16(vv - __bfloat162float(vh));
    }
}

// ===========================================================================
// Attention via mma.sync bf16 split. Fixed-shift softmax (no max, no rescale).
// ===========================================================================
#define OKHI 0u
#define OKLO 8192u
#define OQHI 16384u
#define OQLO 24576u
#define OVHI 32768u
#define OVLO 40960u
#define OPHI 49152u
#define OPLO 57344u
#define ATTN_SMEM 65536u

// load a 64x64 bf16 tile into XOR-swizzled smem (granule g of row r -> g^(r&7))
__device__ __forceinline__ void ld_tile(char* sm, uint32_t dst,
                                        const __nv_bfloat16* __restrict__ src,
                                        int rstride) {
#pragma unroll
    for (int i = 0; i < 2; ++i) {
        int idx = threadIdx.x + i * 256;      // 512 granules of 16B
        int r = idx >> 3, cc = idx & 7;
        uint32_t off = (uint32_t)r * 128u + (uint32_t)((cc ^ (r & 7)) << 4);
        *(uint4*)(sm + dst + off) = *(const uint4*)(src + (size_t)r * rstride + cc * 8);
    }
}

// D(64x64) += A(64x64) * B(64x64)^T with 2-term bf16 split (hh + lh + hl).
// A rows m0..m0+15 for this warp; B rows (n) n0..n0+31. Acc into S[4][4].
__device__ __forceinline__ void gemm_split(uint32_t sb, uint32_t aHi, uint32_t aLo,
                                           uint32_t bHi, uint32_t bLo,
                                           int m0, int n0, float S[4][4])
{
    const int lane = threadIdx.x & 31;
    const int arow  = m0 + (lane & 15);
    const int brow0 = n0 + (lane & 7) + ((lane >> 4) << 3);
    const int brow1 = brow0 + 16;
#pragma unroll
    for (int ks = 0; ks < 4; ++ks) {
        const int kgA = 2*ks + (lane >> 4);
        const int kgB = 2*ks + ((lane >> 3) & 1);
        uint32_t aoff  = (uint32_t)arow*128u  + (uint32_t)((kgA ^ (arow  & 7)) << 4);
        uint32_t boff0 = (uint32_t)brow0*128u + (uint32_t)((kgB ^ (brow0 & 7)) << 4);
        uint32_t boff1 = (uint32_t)brow1*128u + (uint32_t)((kgB ^ (brow1 & 7)) << 4);
        uint32_t ah[4], al[4], bh0[4], bh1[4], bl0[4], bl1[4];
        ldsm_x4(ah,  sb + aHi + aoff);
        ldsm_x4(al,  sb + aLo + aoff);
        ldsm_x4(bh0, sb + bHi + boff0);
        ldsm_x4(bh1, sb + bHi + boff1);
        ldsm_x4(bl0, sb + bLo + boff0);
        ldsm_x4(bl1, sb + bLo + boff1);
#pragma unroll
        for (int j = 0; j < 4; ++j) {
            const uint32_t* bh = (j < 2) ? bh0 : bh1;
            const uint32_t* bl = (j < 2) ? bl0 : bl1;
            const int o = (j & 1) * 2;
            mma16816(S[j], ah, bh + o);
            mma16816(S[j], al, bh + o);
            mma16816(S[j], ah, bl + o);
        }
    }
}

__device__ __forceinline__ void store_p(char* sm, int row, int col,
                                        float p0, float p1) {
    __nv_bfloat16 h0 = __float2bfloat16(p0), h1 = __float2bfloat16(p1);
    float r0 = p0 - __bfloat162float(h0), r1 = p1 - __bfloat162float(h1);
    uint32_t hv = (uint32_t)__bfloat16_as_ushort(h0) |
                  ((uint32_t)__bfloat16_as_ushort(h1) << 16);
    uint32_t lv = (uint32_t)__bfloat16_as_ushort(__float2bfloat16(r0)) |
                  ((uint32_t)__bfloat16_as_ushort(__float2bfloat16(r1)) << 16);
    uint32_t g = (uint32_t)(col >> 3);
    uint32_t off = (uint32_t)row*128u + ((g ^ (uint32_t)(row & 7)) << 4)
                 + (uint32_t)((col & 7) * 2);
    *(uint32_t*)(sm + OPHI + off) = hv;
    *(uint32_t*)(sm + OPLO + off) = lv;
}

__global__ __launch_bounds__(256) void attn_kernel(float* __restrict__ out)
{
    extern __shared__ char sm[];
    const uint32_t sb = smem_u32(sm);
    const int tid  = threadIdx.x;
    const int lane = tid & 31;
    const int wid  = tid >> 5;
    const int wr = wid & 3, wc = wid >> 2;
    const int m0 = wr * 16, n0 = wc * 32;
    const int bb = blockIdx.y;

    const __nv_bfloat16* Khi = g_Khi + (size_t)bb * T_ * HS_;
    const __nv_bfloat16* Klo = g_Klo + (size_t)bb * T_ * HS_;
    const __nv_bfloat16* Qhi = g_Qhi + (size_t)bb * T_ * HS_;
    const __nv_bfloat16* Qlo = g_Qlo + (size_t)bb * T_ * HS_;
    const __nv_bfloat16* Vth = g_Vthi + (size_t)bb * HS_ * T_;
    const __nv_bfloat16* Vtl = g_Vtlo + (size_t)bb * HS_ * T_;

    for (int pass = 0; pass < 2; ++pass) {
        const int ti = pass ? 63 - (int)blockIdx.x : (int)blockIdx.x;
        const int t0 = ti * 64;

        __syncthreads();                       // prior pass fully done with smem
        ld_tile(sm, OKHI, Khi + (size_t)t0 * HS_, HS_);
        ld_tile(sm, OKLO, Klo + (size_t)t0 * HS_, HS_);

        float Oa[4][4];
#pragma unroll
        for (int j = 0; j < 4; ++j)
#pragma unroll
            for (int q = 0; q < 4; ++q) Oa[j][q] = 0.f;
        float l0 = 0.f, l1 = 0.f;
        const int rr0 = t0 + m0 + (lane >> 2), rr1 = rr0 + 8;

        for (int s0 = 0; s0 <= t0; s0 += 64) {
            __syncthreads();                   // prev GEMM2 done -> overwrite Q/V
            ld_tile(sm, OQHI, Qhi + (size_t)s0 * HS_, HS_);
            ld_tile(sm, OQLO, Qlo + (size_t)s0 * HS_, HS_);
            ld_tile(sm, OVHI, Vth + s0, T_);
            ld_tile(sm, OVLO, Vtl + s0, T_);
            __syncthreads();

            float S[4][4];
#pragma unroll
            for (int j = 0; j < 4; ++j)
#pragma unroll
                for (int q = 0; q < 4; ++q) S[j][q] = 0.f;
            gemm_split(sb, OKHI, OKLO, OQHI, OQLO, m0, n0, S);

            const bool diag = (s0 == t0);
#pragma unroll
            for (int j = 0; j < 4; ++j) {
                const int cl = n0 + 8*j + 2*(lane & 3);   // local col
                const int cg = s0 + cl;                   // global col
                float p00 = __expf(S[j][0]);
                float p01 = __expf(S[j][1]);
                float p10 = __expf(S[j][2]);
                float p11 = __expf(S[j][3]);
                if (diag) {
                    if (cg     > rr0) p00 = 0.f;
                    if (cg + 1 > rr0) p01 = 0.f;
                    if (cg     > rr1) p10 = 0.f;
                    if (cg + 1 > rr1) p11 = 0.f;
                }
                l0 += p00 + p01;
                l1 += p10 + p11;
                store_p(sm, m0 + (lane >> 2),     cl, p00, p01);
                store_p(sm, m0 + (lane >> 2) + 8, cl, p10, p11);
            }
            __syncthreads();                   // P visible to all warps

            gemm_split(sb, OPHI, OPLO, OVHI, OVLO, m0, n0, Oa);
        }

        // epilogue: reduce l across lanes + the two wc warps, scale, store
        __syncthreads();                       // last GEMM2 done; smem reusable
        float* l_sm = (float*)(sm + OQHI);
        l0 += __shfl_xor_sync(0xffffffffu, l0, 1);
        l0 += __shfl_xor_sync(0xffffffffu, l0, 2);
        l1 += __shfl_xor_sync(0xffffffffu, l1, 1);
        l1 += __shfl_xor_sync(0xffffffffu, l1, 2);
        if ((lane & 3) == 0) {
            l_sm[wc*64 + m0 + (lane >> 2)]     = l0;
            l_sm[wc*64 + m0 + (lane >> 2) + 8] = l1;
        }
        __syncthreads();
        {
            const int rl = m0 + (lane >> 2);
            const float inv0 = 1.f / (l_sm[rl]     + l_sm[64 + rl]);
            const float inv1 = 1.f / (l_sm[rl + 8] + l_sm[64 + rl + 8]);
            float2* b0p = (float2*)(out + ((size_t)bb * T_ + t0 + rl)     * HS_);
            float2* b1p = (float2*)(out + ((size_t)bb * T_ + t0 + rl + 8) * HS_);
#pragma unroll
            for (int j = 0; j < 4; ++j) {
                const int c = n0 + 8*j + 2*(lane & 3);
                b0p[c >> 1] = make_float2(Oa[j][0]*inv0, Oa[j][1]*inv0);
                b1p[c >> 1] = make_float2(Oa[j][2]*inv1, Oa[j][3]*inv1);
            }
        }
    }
}

// ---------------------------------------------------------------------------
extern "C" void kernel_launch(void* const* d_in, const int* in_sizes, int n_in,
                              void* d_out, int out_size)
{
    (void)in_sizes; (void)n_in; (void)out_size;
    const float* x  = (const float*)d_in[0];
    const float* Wk = (const float*)d_in[1];
    const float* bk = (const float*)d_in[2];
    const float* Wq = (const float*)d_in[3];
    const float* bq = (const float*)d_in[4];
    const float* Wv = (const float*)d_in[5];
    const float* bv = (const float*)d_in[6];
    float* out = (float*)d_out;

    cudaFuncSetAttribute(attn_kernel,
                         cudaFuncAttributeMaxDynamicSharedMemorySize, ATTN_SMEM);

    proj_kernel<<<BT_/32, 256>>>(x, Wk, bk, Wq, bq, Wv, bv);
    attn_kernel<<<dim3(32, B_), 256, ATTN_SMEM>>>(out);
}

// round 8
// speedup vs baseline: 1.7518x; 1.5142x over previous
#include <cuda_runtime.h>
#include <cuda_bf16.h>
#include <cstdint>
#include <math_constants.h>

#define B_   4
#define T_   4096
#define EMB_ 768
#define HS_  64
#define BT_  (B_*T_)

// bf16 split operands produced by proj, consumed by attention MMAs.
// All stored natural [row][h] -> every proj write coalesced.
__device__ __nv_bfloat16 g_Khi[BT_*HS_];
__device__ __nv_bfloat16 g_Klo[BT_*HS_];
__device__ __nv_bfloat16 g_Qhi[BT_*HS_];
__device__ __nv_bfloat16 g_Qlo[BT_*HS_];
__device__ __nv_bfloat16 g_Vhi[BT_*HS_];
__device__ __nv_bfloat16 g_Vlo[BT_*HS_];

__device__ __forceinline__ uint32_t smem_u32(const void* p) {
    uint32_t a;
    asm("{ .reg .u64 t; cvta.to.shared.u64 t, %1; cvt.u32.u64 %0, t; }"
        : "=r"(a) : "l"(p));
    return a;
}
__device__ __forceinline__ void ldsm_x4(uint32_t* r, uint32_t addr) {
    asm volatile("ldmatrix.sync.aligned.m8n8.x4.shared.b16 {%0,%1,%2,%3}, [%4];"
        : "=r"(r[0]), "=r"(r[1]), "=r"(r[2]), "=r"(r[3]) : "r"(addr));
}
__device__ __forceinline__ void ldsm_x4_t(uint32_t* r, uint32_t addr) {
    asm volatile("ldmatrix.sync.aligned.m8n8.x4.trans.shared.b16 {%0,%1,%2,%3}, [%4];"
        : "=r"(r[0]), "=r"(r[1]), "=r"(r[2]), "=r"(r[3]) : "r"(addr));
}
__device__ __forceinline__ void mma16816(float* d, const uint32_t* a, const uint32_t* b) {
    asm volatile("mma.sync.aligned.m16n8k16.row.col.f32.bf16.bf16.f32 "
        "{%0,%1,%2,%3},{%4,%5,%6,%7},{%8,%9},{%0,%1,%2,%3};"
        : "+f"(d[0]), "+f"(d[1]), "+f"(d[2]), "+f"(d[3])
        : "r"(a[0]), "r"(a[1]), "r"(a[2]), "r"(a[3]), "r"(b[0]), "r"(b[1]));
}

// ===========================================================================
// Projection (SIMT fp32). Epilogue emits bf16 hi/lo splits, all coalesced.
// ===========================================================================
__global__ __launch_bounds__(256) void proj_kernel(
    const float* __restrict__ x,
    const float* __restrict__ Wk, const float* __restrict__ bk,
    const float* __restrict__ Wq, const float* __restrict__ bq,
    const float* __restrict__ Wv, const float* __restrict__ bv)
{
    __shared__ float sx[32][64];
    const int row0 = blockIdx.x * 32;
    const int c  = threadIdx.x & 63;
    const int rg = threadIdx.x >> 6;

    float ak[8], aq[8], av[8];
#pragma unroll
    for (int i = 0; i < 8; ++i) { ak[i] = 0.f; aq[i] = 0.f; av[i] = 0.f; }

    for (int e0 = 0; e0 < EMB_; e0 += 64) {
        __syncthreads();
#pragma unroll
        for (int i = threadIdx.x; i < 512; i += 256) {
            int r = i >> 4, cc = i & 15;
            ((float4*)sx[r])[cc] =
                ((const float4*)(x + (size_t)(row0 + r) * EMB_ + e0))[cc];
        }
        __syncthreads();
#pragma unroll 4
        for (int e = 0; e < 64; e += 4) {
            const float* wkp = Wk + (size_t)(e0 + e) * HS_ + c;
            const float* wqp = Wq + (size_t)(e0 + e) * HS_ + c;
            const float* wvp = Wv + (size_t)(e0 + e) * HS_ + c;
            float wk0 = wkp[0], wk1 = wkp[HS_], wk2 = wkp[2*HS_], wk3 = wkp[3*HS_];
            float wq0 = wqp[0], wq1 = wqp[HS_], wq2 = wqp[2*HS_], wq3 = wqp[3*HS_];
            float wv0 = wvp[0], wv1 = wvp[HS_], wv2 = wvp[2*HS_], wv3 = wvp[3*HS_];
#pragma unroll
            for (int i = 0; i < 8; ++i) {
                float4 xv = *(const float4*)(&sx[rg*8 + i][e]);
                ak[i] += xv.x*wk0; ak[i] += xv.y*wk1; ak[i] += xv.z*wk2; ak[i] += xv.w*wk3;
                aq[i] += xv.x*wq0; aq[i] += xv.y*wq1; aq[i] += xv.z*wq2; aq[i] += xv.w*wq3;
                av[i] += xv.x*wv0; av[i] += xv.y*wv1; av[i] += xv.z*wv2; av[i] += xv.w*wv3;
            }
        }
    }

    const float bkv = bk[c], bqv = bq[c], bvv = bv[c];
#pragma unroll
    for (int i = 0; i < 8; ++i) {
        int row = row0 + rg*8 + i;
        float kv = ak[i] + bkv, qv = aq[i] + bqv, vv = av[i] + bvv;
        __nv_bfloat16 kh = __float2bfloat16(kv);
        __nv_bfloat16 qh = __float2bfloat16(qv);
        __nv_bfloat16 vh = __float2bfloat16(vv);
        size_t o = (size_t)row * HS_ + c;
        g_Khi[o] = kh;
        g_Klo[o] = __float2bfloat16(kv - __bfloat162float(kh));
        g_Qhi[o] = qh;
        g_Qlo[o] = __float2bfloat16(qv - __bfloat162float(qh));
        g_Vhi[o] = vh;
        g_Vlo[o] = __float2bfloat16(vv - __bfloat162float(vh));
    }
}

// ===========================================================================
// Attention: mma.sync bf16 split, fixed-shift softmax, double-buffered Q/V.
// smem map: K 0/8192 | buf{0,1}: Q hi/lo, V hi/lo (4x8KB each) | P hi/lo
// ===========================================================================
#define OKHI  0u
#define OKLO  8192u
#define OBUF(b) (16384u + (uint32_t)(b) * 32768u)   // QHI,QLO,VHI,VLO @ +0,8K,16K,24K
#define OPHI  81920u
#define OPLO  90112u
#define ATTN_SMEM 98304u

// load a 64x64 bf16 tile into XOR-swizzled smem (granule cc of row r -> cc^(r&7))
__device__ __forceinline__ void ld_tile(char* sm, uint32_t dst,
                                        const __nv_bfloat16* __restrict__ src,
                                        int rstride) {
#pragma unroll
    for (int i = 0; i < 2; ++i) {
        int idx = threadIdx.x + i * 256;
        int r = idx >> 3, cc = idx & 7;
        uint32_t off = (uint32_t)r * 128u + (uint32_t)((cc ^ (r & 7)) << 4);
        *(uint4*)(sm + dst + off) = *(const uint4*)(src + (size_t)r * rstride + cc * 8);
    }
}

// GEMM1: S(64x64) += A(K tile) * B(Q tile)^T, 2-term bf16 split (hh+lh+hl).
__device__ __forceinline__ void gemm_split(uint32_t sb, uint32_t aHi, uint32_t aLo,
                                           uint32_t bHi, uint32_t bLo,
                                           int m0, int n0, float S[4][4])
{
    const int lane = threadIdx.x & 31;
    const int arow  = m0 + (lane & 15);
    const int brow0 = n0 + (lane & 7) + ((lane >> 4) << 3);
    const int brow1 = brow0 + 16;
#pragma unroll
    for (int ks = 0; ks < 4; ++ks) {
        const int kgA = 2*ks + (lane >> 4);
        const int kgB = 2*ks + ((lane >> 3) & 1);
        uint32_t aoff  = (uint32_t)arow*128u  + (uint32_t)((kgA ^ (arow  & 7)) << 4);
        uint32_t boff0 = (uint32_t)brow0*128u + (uint32_t)((kgB ^ (brow0 & 7)) << 4);
        uint32_t boff1 = (uint32_t)brow1*128u + (uint32_t)((kgB ^ (brow1 & 7)) << 4);
        uint32_t ah[4], al[4], bh0[4], bh1[4], bl0[4], bl1[4];
        ldsm_x4(ah,  sb + aHi + aoff);
        ldsm_x4(al,  sb + aLo + aoff);
        ldsm_x4(bh0, sb + bHi + boff0);
        ldsm_x4(bh1, sb + bHi + boff1);
        ldsm_x4(bl0, sb + bLo + boff0);
        ldsm_x4(bl1, sb + bLo + boff1);
#pragma unroll
        for (int j = 0; j < 4; ++j) {
            const uint32_t* bh = (j < 2) ? bh0 : bh1;
            const uint32_t* bl = (j < 2) ? bl0 : bl1;
            const int o = (j & 1) * 2;
            mma16816(S[j], ah, bh + o);
            mma16816(S[j], al, bh + o);
            mma16816(S[j], ah, bl + o);
        }
    }
}

// GEMM2: O += P * V, V in natural [s][h] layout via trans-ldmatrix.
__device__ __forceinline__ void gemm2_split(uint32_t sb, uint32_t pHi, uint32_t pLo,
                                            uint32_t vHi, uint32_t vLo,
                                            int m0, int n0, float O[4][4])
{
    const int lane = threadIdx.x & 31;
    const int arow = m0 + (lane & 15);
    const int g = lane >> 3, rr = lane & 7;
#pragma unroll
    for (int ks = 0; ks < 4; ++ks) {
        const int kgA = 2*ks + (lane >> 4);
        uint32_t aoff = (uint32_t)arow*128u + (uint32_t)((kgA ^ (arow & 7)) << 4);
        uint32_t ah[4], al[4];
        ldsm_x4(ah, sb + pHi + aoff);
        ldsm_x4(al, sb + pLo + aoff);
        const int s_row = ks*16 + ((g & 1) << 3) + rr;
        const uint32_t vrow = (uint32_t)s_row * 128u;
        const uint32_t sw = (uint32_t)(s_row & 7);
#pragma unroll
        for (int half = 0; half < 2; ++half) {
            const int h0 = n0 + half*16 + ((g >> 1) << 3);
            uint32_t voff = vrow + ((((uint32_t)h0 >> 3) ^ sw) << 4);
            uint32_t vh[4], vl[4];
            ldsm_x4_t(vh, sb + vHi + voff);
            ldsm_x4_t(vl, sb + vLo + voff);
#pragma unroll
            for (int jj = 0; jj < 2; ++jj) {
                const int j = half*2 + jj;
                mma16816(O[j], ah, vh + jj*2);
                mma16816(O[j], al, vh + jj*2);
                mma16816(O[j], ah, vl + jj*2);
            }
        }
    }
}

__device__ __forceinline__ void store_p(char* sm, int row, int col,
                                        float p0, float p1) {
    __nv_bfloat16 h0 = __float2bfloat16(p0), h1 = __float2bfloat16(p1);
    float r0 = p0 - __bfloat162float(h0), r1 = p1 - __bfloat162float(h1);
    uint32_t hv = (uint32_t)__bfloat16_as_ushort(h0) |
                  ((uint32_t)__bfloat16_as_ushort(h1) << 16);
    uint32_t lv = (uint32_t)__bfloat16_as_ushort(__float2bfloat16(r0)) |
                  ((uint32_t)__bfloat16_as_ushort(__float2bfloat16(r1)) << 16);
    uint32_t g = (uint32_t)(col >> 3);
    uint32_t off = (uint32_t)row*128u + ((g ^ (uint32_t)(row & 7)) << 4)
                 + (uint32_t)((col & 7) * 2);
    *(uint32_t*)(sm + OPHI + off) = hv;
    *(uint32_t*)(sm + OPLO + off) = lv;
}

__global__ __launch_bounds__(256) void attn_kernel(float* __restrict__ out)
{
    extern __shared__ char sm[];
    const uint32_t sb = smem_u32(sm);
    const int tid  = threadIdx.x;
    const int lane = tid & 31;
    const int wid  = tid >> 5;
    const int wr = wid & 3, wc = wid >> 2;
    const int m0 = wr * 16, n0 = wc * 32;
    const int bb = blockIdx.y;

    const __nv_bfloat16* Khi = g_Khi + (size_t)bb * T_ * HS_;
    const __nv_bfloat16* Klo = g_Klo + (size_t)bb * T_ * HS_;
    const __nv_bfloat16* Qhi = g_Qhi + (size_t)bb * T_ * HS_;
    const __nv_bfloat16* Qlo = g_Qlo + (size_t)bb * T_ * HS_;
    const __nv_bfloat16* Vhi = g_Vhi + (size_t)bb * T_ * HS_;
    const __nv_bfloat16* Vlo = g_Vlo + (size_t)bb * T_ * HS_;

    for (int pass = 0; pass < 2; ++pass) {
        const int ti = pass ? 63 - (int)blockIdx.x : (int)blockIdx.x;
        const int t0 = ti * 64;

        __syncthreads();                       // prior pass fully done with smem
        ld_tile(sm, OKHI, Khi + (size_t)t0 * HS_, HS_);
        ld_tile(sm, OKLO, Klo + (size_t)t0 * HS_, HS_);
        ld_tile(sm, OBUF(0) +     0u, Qhi, HS_);   // s0 = 0 tiles into buf 0
        ld_tile(sm, OBUF(0) +  8192u, Qlo, HS_);
        ld_tile(sm, OBUF(0) + 16384u, Vhi, HS_);
        ld_tile(sm, OBUF(0) + 24576u, Vlo, HS_);

        float Oa[4][4];
#pragma unroll
        for (int j = 0; j < 4; ++j)
#pragma unroll
            for (int q = 0; q < 4; ++q) Oa[j][q] = 0.f;
        float l0 = 0.f, l1 = 0.f;
        const int rr0 = t0 + m0 + (lane >> 2), rr1 = rr0 + 8;

        __syncthreads();                       // buf0 + K ready

        for (int s0 = 0, it = 0; s0 <= t0; s0 += 64, ++it) {
            const uint32_t cb = OBUF(it & 1);
            const uint32_t nb = OBUF(1 - (it & 1));
            const int sn = s0 + 64;
            const bool hasNext = (sn <= t0);

            // 1) issue next-tile LDGs (latency hidden under GEMM1)
            uint4 pf[8];
            if (hasNext) {
#pragma unroll
                for (int t4 = 0; t4 < 4; ++t4) {
                    const __nv_bfloat16* s4 =
                        (t4 == 0 ? Qhi : t4 == 1 ? Qlo : t4 == 2 ? Vhi : Vlo)
                        + (size_t)sn * HS_;
#pragma unroll
                    for (int i = 0; i < 2; ++i) {
                        int idx = tid + i * 256, r = idx >> 3, cc = idx & 7;
                        pf[t4*2 + i] = *(const uint4*)(s4 + (size_t)r * HS_ + cc * 8);
                    }
                }
            }

            // 2) GEMM1: S = K * Q^T
            float S[4][4];
#pragma unroll
            for (int j = 0; j < 4; ++j)
#pragma unroll
                for (int q = 0; q < 4; ++q) S[j][q] = 0.f;
            gemm_split(sb, OKHI, OKLO, cb, cb + 8192u, m0, n0, S);

            // 3) stage next tiles into the idle buffer
            if (hasNext) {
#pragma unroll
                for (int t4 = 0; t4 < 4; ++t4) {
                    const uint32_t dst = nb + (uint32_t)t4 * 8192u;
#pragma unroll
                    for (int i = 0; i < 2; ++i) {
                        int idx = tid + i * 256, r = idx >> 3, cc = idx & 7;
                        uint32_t off = (uint32_t)r * 128u
                                     + (uint32_t)((cc ^ (r & 7)) << 4);
                        *(uint4*)(sm + dst + off) = pf[t4*2 + i];
                    }
                }
            }

            // 4) softmax: exp, causal mask on diagonal tile, P -> smem
            const bool diag = (s0 == t0);
#pragma unroll
            for (int j = 0; j < 4; ++j) {
                const int cl = n0 + 8*j + 2*(lane & 3);
                const int cg = s0 + cl;
                float p00 = __expf(S[j][0]);
                float p01 = __expf(S[j][1]);
                float p10 = __expf(S[j][2]);
                float p11 = __expf(S[j][3]);
                if (diag) {
                    if (cg     > rr0) p00 = 0.f;
                    if (cg + 1 > rr0) p01 = 0.f;
                    if (cg     > rr1) p10 = 0.f;
                    if (cg + 1 > rr1) p11 = 0.f;
                }
                l0 += p00 + p01;
                l1 += p10 + p11;
                store_p(sm, m0 + (lane >> 2),     cl, p00, p01);
                store_p(sm, m0 + (lane >> 2) + 8, cl, p10, p11);
            }
            __syncthreads();                   // P visible to all warps

            // 5) GEMM2: O += P * V (trans-ldmatrix on natural-layout V)
            gemm2_split(sb, OPHI, OPLO, cb + 16384u, cb + 24576u, m0, n0, Oa);
            __syncthreads();                   // iter done: buffers reusable
        }

        // epilogue: reduce l, scale, store (K region reused for l exchange)
        float* l_sm = (float*)(sm + OKHI);
        l0 += __shfl_xor_sync(0xffffffffu, l0, 1);
        l0 += __shfl_xor_sync(0xffffffffu, l0, 2);
        l1 += __shfl_xor_sync(0xffffffffu, l1, 1);
        l1 += __shfl_xor_sync(0xffffffffu, l1, 2);
        if ((lane & 3) == 0) {
            l_sm[wc*64 + m0 + (lane >> 2)]     = l0;
            l_sm[wc*64 + m0 + (lane >> 2) + 8] = l1;
        }
        __syncthreads();
        {
            const int rl = m0 + (lane >> 2);
            const float inv0 = 1.f / (l_sm[rl]     + l_sm[64 + rl]);
            const float inv1 = 1.f / (l_sm[rl + 8] + l_sm[64 + rl + 8]);
            float2* b0p = (float2*)(out + ((size_t)bb * T_ + t0 + rl)     * HS_);
            float2* b1p = (float2*)(out + ((size_t)bb * T_ + t0 + rl + 8) * HS_);
#pragma unroll
            for (int j = 0; j < 4; ++j) {
                const int c = n0 + 8*j + 2*(lane & 3);
                b0p[c >> 1] = make_float2(Oa[j][0]*inv0, Oa[j][1]*inv0);
                b1p[c >> 1] = make_float2(Oa[j][2]*inv1, Oa[j][3]*inv1);
            }
        }
    }
}

// ---------------------------------------------------------------------------
extern "C" void kernel_launch(void* const* d_in, const int* in_sizes, int n_in,
                              void* d_out, int out_size)
{
    (void)in_sizes; (void)n_in; (void)out_size;
    const float* x  = (const float*)d_in[0];
    const float* Wk = (const float*)d_in[1];
    const float* bk = (const float*)d_in[2];
    const float* Wq = (const float*)d_in[3];
    const float* bq = (const float*)d_in[4];
    const float* Wv = (const float*)d_in[5];
    const float* bv = (const float*)d_in[6];
    float* out = (float*)d_out;

    cudaFuncSetAttribute(attn_kernel,
                         cudaFuncAttributeMaxDynamicSharedMemorySize, ATTN_SMEM);

    proj_kernel<<<BT_/32, 256>>>(x, Wk, bk, Wq, bq, Wv, bv);
    attn_kernel<<<dim3(32, B_), 256, ATTN_SMEM>>>(out);
}

// round 9
// speedup vs baseline: 3.0241x; 1.7262x over previous
#include <cuda_runtime.h>
#include <cuda_bf16.h>
#include <cstdint>
#include <math_constants.h>

#define B_   4
#define T_   4096
#define EMB_ 768
#define HS_  64
#define BT_  (B_*T_)

// bf16 split operands. K/Q/V natural [row][h]; W converted to [k][n0..191].
__device__ __nv_bfloat16 g_Khi[BT_*HS_];
__device__ __nv_bfloat16 g_Klo[BT_*HS_];
__device__ __nv_bfloat16 g_Qhi[BT_*HS_];
__device__ __nv_bfloat16 g_Qlo[BT_*HS_];
__device__ __nv_bfloat16 g_Vhi[BT_*HS_];
__device__ __nv_bfloat16 g_Vlo[BT_*HS_];
__device__ __nv_bfloat16 g_Whi[EMB_*192];
__device__ __nv_bfloat16 g_Wlo[EMB_*192];

__device__ __forceinline__ uint32_t smem_u32(const void* p) {
    uint32_t a;
    asm("{ .reg .u64 t; cvta.to.shared.u64 t, %1; cvt.u32.u64 %0, t; }"
        : "=r"(a) : "l"(p));
    return a;
}
__device__ __forceinline__ void ldsm_x4(uint32_t* r, uint32_t addr) {
    asm volatile("ldmatrix.sync.aligned.m8n8.x4.shared.b16 {%0,%1,%2,%3}, [%4];"
        : "=r"(r[0]), "=r"(r[1]), "=r"(r[2]), "=r"(r[3]) : "r"(addr));
}
__device__ __forceinline__ void ldsm_x4_t(uint32_t* r, uint32_t addr) {
    asm volatile("ldmatrix.sync.aligned.m8n8.x4.trans.shared.b16 {%0,%1,%2,%3}, [%4];"
        : "=r"(r[0]), "=r"(r[1]), "=r"(r[2]), "=r"(r[3]) : "r"(addr));
}
__device__ __forceinline__ void mma16816(float* d, const uint32_t* a, const uint32_t* b) {
    asm volatile("mma.sync.aligned.m16n8k16.row.col.f32.bf16.bf16.f32 "
        "{%0,%1,%2,%3},{%4,%5,%6,%7},{%8,%9},{%0,%1,%2,%3};"
        : "+f"(d[0]), "+f"(d[1]), "+f"(d[2]), "+f"(d[3])
        : "r"(a[0]), "r"(a[1]), "r"(a[2]), "r"(a[3]), "r"(b[0]), "r"(b[1]));
}
__device__ __forceinline__ uint32_t pack_bf16(float a, float b) {
    return (uint32_t)__bfloat16_as_ushort(__float2bfloat16(a)) |
           ((uint32_t)__bfloat16_as_ushort(__float2bfloat16(b)) << 16);
}

// ===========================================================================
// W converter: fp32 [768x64] x3 -> bf16 hi/lo [768][192] (k-major rows).
// ===========================================================================
__global__ __launch_bounds__(256) void wconv_kernel(
    const float* __restrict__ Wk, const float* __restrict__ Wq,
    const float* __restrict__ Wv)
{
    const int e = blockIdx.x * 256 + threadIdx.x;   // 0..49151
    const int k = e >> 6, n = e & 63;
#pragma unroll
    for (int mat = 0; mat < 3; ++mat) {
        const float* src = (mat == 0) ? Wk : (mat == 1) ? Wq : Wv;
        float v = src[e];
        __nv_bfloat16 h = __float2bfloat16(v);
        size_t o = (size_t)k * 192 + mat * 64 + n;
        g_Whi[o] = h;
        g_Wlo[o] = __float2bfloat16(v - __bfloat162float(h));
    }
}

// ===========================================================================
// Tensorized projection: [128 x 768] @ [768 x 192] per block, bf16 3-split.
// smem: x hi/lo 16KB+16KB | W tiles 3 mats x (hi,lo) x 8KB = 48KB -> 80KB.
// ===========================================================================
#define OXH 0u
#define OXL 16384u
#define OWT 32768u
#define PROJ_SMEM 81920u

__global__ __launch_bounds__(256) void proj_kernel(
    const float* __restrict__ x,
    const float* __restrict__ bk, const float* __restrict__ bq,
    const float* __restrict__ bv)
{
    extern __shared__ char sm[];
    const uint32_t sb = smem_u32(sm);
    const int tid = threadIdx.x, lane = tid & 31, wid = tid >> 5;
    const int m0 = (wid & 3) * 32, n0 = (wid >> 2) * 96;
    const int row0 = blockIdx.x * 128;

    float acc[2][12][4];
#pragma unroll
    for (int a = 0; a < 2; ++a)
#pragma unroll
        for (int b = 0; b < 12; ++b)
#pragma unroll
            for (int c = 0; c < 4; ++c) acc[a][b][c] = 0.f;

    for (int kc = 0; kc < 12; ++kc) {
        __syncthreads();                        // prev MMA done with smem
        // W bf16 -> swizzled smem tiles (per matrix, 64k x 64n, 128B rows)
#pragma unroll
        for (int hl = 0; hl < 2; ++hl) {
            const __nv_bfloat16* gw = hl ? g_Wlo : g_Whi;
#pragma unroll
            for (int i = 0; i < 6; ++i) {
                int idx = tid + i * 256;        // 1536 granules of 8 bf16
                int k = idx / 24, nc = (idx % 24) * 8;
                uint4 v = *(const uint4*)(gw + (size_t)(kc*64 + k) * 192 + nc);
                int mat = nc >> 6, ln = nc & 63;
                uint32_t dst = OWT + (uint32_t)mat*16384u + (uint32_t)hl*8192u
                             + (uint32_t)k*128u
                             + (uint32_t)((((ln >> 3) ^ (k & 7))) << 4);
                *(uint4*)(sm + dst) = v;
            }
        }
        // x fp32 -> bf16 hi/lo -> swizzled smem (128 rows x 64 k)
#pragma unroll
        for (int i = 0; i < 8; ++i) {
            int idx = tid + i * 256;            // 2048 float4
            int r = idx >> 4, c4 = (idx & 15) * 4;
            float4 v = *(const float4*)(x + (size_t)(row0 + r) * EMB_ + kc*64 + c4);
            __nv_bfloat16 hx = __float2bfloat16(v.x), hy = __float2bfloat16(v.y);
            __nv_bfloat16 hz = __float2bfloat16(v.z), hw = __float2bfloat16(v.w);
            uint32_t h01 = (uint32_t)__bfloat16_as_ushort(hx) |
                           ((uint32_t)__bfloat16_as_ushort(hy) << 16);
            uint32_t h23 = (uint32_t)__bfloat16_as_ushort(hz) |
                           ((uint32_t)__bfloat16_as_ushort(hw) << 16);
            uint32_t l01 = pack_bf16(v.x - __bfloat162float(hx),
                                     v.y - __bfloat162float(hy));
            uint32_t l23 = pack_bf16(v.z - __bfloat162float(hz),
                                     v.w - __bfloat162float(hw));
            uint32_t off = (uint32_t)r * 128u
                         + (uint32_t)((((c4 >> 3) ^ (r & 7))) << 4)
                         + (uint32_t)((c4 & 7) * 2);
            *(uint2*)(sm + OXH + off) = make_uint2(h01, h23);
            *(uint2*)(sm + OXL + off) = make_uint2(l01, l23);
        }
        __syncthreads();

        // MMA: 4 k16 steps; A = x (row-major frags), B = W via trans-ldmatrix
#pragma unroll
        for (int ks = 0; ks < 4; ++ks) {
            uint32_t ah[2][4], al[2][4];
#pragma unroll
            for (int mt = 0; mt < 2; ++mt) {
                int arow = m0 + mt*16 + (lane & 15);
                int kg = 2*ks + (lane >> 4);
                uint32_t aoff = (uint32_t)arow*128u
                              + (uint32_t)(((kg ^ (arow & 7))) << 4);
                ldsm_x4(ah[mt], sb + OXH + aoff);
                ldsm_x4(al[mt], sb + OXL + aoff);
            }
            const int g = lane >> 3, rr = lane & 7;
            const int krow = ks*16 + ((g & 1) << 3) + rr;
#pragma unroll
            for (int grp = 0; grp < 6; ++grp) {
                int hglob = n0 + grp*16 + ((g >> 1) << 3);
                int mat = hglob >> 6, lc = hglob & 63;
                uint32_t base = OWT + (uint32_t)mat * 16384u;
                uint32_t voff = (uint32_t)krow*128u
                              + (uint32_t)((((lc >> 3) ^ (krow & 7))) << 4);
                uint32_t wh[4], wl[4];
                ldsm_x4_t(wh, sb + base + voff);
                ldsm_x4_t(wl, sb + base + 8192u + voff);
#pragma unroll
                for (int mt = 0; mt < 2; ++mt)
#pragma unroll
                    for (int jj = 0; jj < 2; ++jj) {
                        float* d = acc[mt][grp*2 + jj];
                        mma16816(d, ah[mt], wh + jj*2);
                        mma16816(d, al[mt], wh + jj*2);
                        mma16816(d, ah[mt], wl + jj*2);
                    }
            }
        }
    }

    // epilogue: bias, bf16 hi/lo split, coalesced-ish uint32 stores
#pragma unroll
    for (int nj = 0; nj < 12; ++nj) {
        const int c0 = n0 + nj*8 + 2*(lane & 3);
        const int mat = c0 >> 6, lc = c0 & 63;
        const float* bp = (mat == 0) ? bk : (mat == 1) ? bq : bv;
        const float b0 = bp[lc], b1 = bp[lc + 1];
        __nv_bfloat16* hp = (mat == 0) ? g_Khi : (mat == 1) ? g_Qhi : g_Vhi;
        __nv_bfloat16* lp = (mat == 0) ? g_Klo : (mat == 1) ? g_Qlo : g_Vlo;
#pragma unroll
        for (int mt = 0; mt < 2; ++mt)
#pragma unroll
            for (int h = 0; h < 2; ++h) {
                const int r = row0 + m0 + mt*16 + (lane >> 2) + h*8;
                float v0 = acc[mt][nj][h*2 + 0] + b0;
                float v1 = acc[mt][nj][h*2 + 1] + b1;
                __nv_bfloat16 h0 = __float2bfloat16(v0);
                __nv_bfloat16 h1 = __float2bfloat16(v1);
                uint32_t hv = (uint32_t)__bfloat16_as_ushort(h0) |
                              ((uint32_t)__bfloat16_as_ushort(h1) << 16);
                uint32_t lv = pack_bf16(v0 - __bfloat162float(h0),
                                        v1 - __bfloat162float(h1));
                size_t o = (size_t)r * HS_ + lc;
                *(uint32_t*)(hp + o) = hv;
                *(uint32_t*)(lp + o) = lv;
            }
    }
}

// ===========================================================================
// Attention (unchanged from R7 pass: mma.sync bf16 split, double-buffered).
// ===========================================================================
#define OKHI  0u
#define OKLO  8192u
#define OBUF(b) (16384u + (uint32_t)(b) * 32768u)
#define OPHI  81920u
#define OPLO  90112u
#define ATTN_SMEM 98304u

__device__ __forceinline__ void ld_tile(char* sm, uint32_t dst,
                                        const __nv_bfloat16* __restrict__ src,
                                        int rstride) {
#pragma unroll
    for (int i = 0; i < 2; ++i) {
        int idx = threadIdx.x + i * 256;
        int r = idx >> 3, cc = idx & 7;
        uint32_t off = (uint32_t)r * 128u + (uint32_t)((cc ^ (r & 7)) << 4);
        *(uint4*)(sm + dst + off) = *(const uint4*)(src + (size_t)r * rstride + cc * 8);
    }
}

__device__ __forceinline__ void gemm_split(uint32_t sb, uint32_t aHi, uint32_t aLo,
                                           uint32_t bHi, uint32_t bLo,
                                           int m0, int n0, float S[4][4])
{
    const int lane = threadIdx.x & 31;
    const int arow  = m0 + (lane & 15);
    const int brow0 = n0 + (lane & 7) + ((lane >> 4) << 3);
    const int brow1 = brow0 + 16;
#pragma unroll
    for (int ks = 0; ks < 4; ++ks) {
        const int kgA = 2*ks + (lane >> 4);
        const int kgB = 2*ks + ((lane >> 3) & 1);
        uint32_t aoff  = (uint32_t)arow*128u  + (uint32_t)((kgA ^ (arow  & 7)) << 4);
        uint32_t boff0 = (uint32_t)brow0*128u + (uint32_t)((kgB ^ (brow0 & 7)) << 4);
        uint32_t boff1 = (uint32_t)brow1*128u + (uint32_t)((kgB ^ (brow1 & 7)) << 4);
        uint32_t ah[4], al[4], bh0[4], bh1[4], bl0[4], bl1[4];
        ldsm_x4(ah,  sb + aHi + aoff);
        ldsm_x4(al,  sb + aLo + aoff);
        ldsm_x4(bh0, sb + bHi + boff0);
        ldsm_x4(bh1, sb + bHi + boff1);
        ldsm_x4(bl0, sb + bLo + boff0);
        ldsm_x4(bl1, sb + bLo + boff1);
#pragma unroll
        for (int j = 0; j < 4; ++j) {
            const uint32_t* bh = (j < 2) ? bh0 : bh1;
            const uint32_t* bl = (j < 2) ? bl0 : bl1;
            const int o = (j & 1) * 2;
            mma16816(S[j], ah, bh + o);
            mma16816(S[j], al, bh + o);
            mma16816(S[j], ah, bl + o);
        }
    }
}

__device__ __forceinline__ void gemm2_split(uint32_t sb, uint32_t pHi, uint32_t pLo,
                                            uint32_t vHi, uint32_t vLo,
                                            int m0, int n0, float O[4][4])
{
    const int lane = threadIdx.x & 31;
    const int arow = m0 + (lane & 15);
    const int g = lane >> 3, rr = lane & 7;
#pragma unroll
    for (int ks = 0; ks < 4; ++ks) {
        const int kgA = 2*ks + (lane >> 4);
        uint32_t aoff = (uint32_t)arow*128u + (uint32_t)((kgA ^ (arow & 7)) << 4);
        uint32_t ah[4], al[4];
        ldsm_x4(ah, sb + pHi + aoff);
        ldsm_x4(al, sb + pLo + aoff);
        const int s_row = ks*16 + ((g & 1) << 3) + rr;
        const uint32_t vrow = (uint32_t)s_row * 128u;
        const uint32_t sw = (uint32_t)(s_row & 7);
#pragma unroll
        for (int half = 0; half < 2; ++half) {
            const int h0 = n0 + half*16 + ((g >> 1) << 3);
            uint32_t voff = vrow + ((((uint32_t)h0 >> 3) ^ sw) << 4);
            uint32_t vh[4], vl[4];
            ldsm_x4_t(vh, sb + vHi + voff);
            ldsm_x4_t(vl, sb + vLo + voff);
#pragma unroll
            for (int jj = 0; jj < 2; ++jj) {
                const int j = half*2 + jj;
                mma16816(O[j], ah, vh + jj*2);
                mma16816(O[j], al, vh + jj*2);
                mma16816(O[j], ah, vl + jj*2);
            }
        }
    }
}

__device__ __forceinline__ void store_p(char* sm, int row, int col,
                                        float p0, float p1) {
    __nv_bfloat16 h0 = __float2bfloat16(p0), h1 = __float2bfloat16(p1);
    uint32_t hv = (uint32_t)__bfloat16_as_ushort(h0) |
                  ((uint32_t)__bfloat16_as_ushort(h1) << 16);
    uint32_t lv = pack_bf16(p0 - __bfloat162float(h0), p1 - __bfloat162float(h1));
    uint32_t g = (uint32_t)(col >> 3);
    uint32_t off = (uint32_t)row*128u + ((g ^ (uint32_t)(row & 7)) << 4)
                 + (uint32_t)((col & 7) * 2);
    *(uint32_t*)(sm + OPHI + off) = hv;
    *(uint32_t*)(sm + OPLO + off) = lv;
}

__global__ __launch_bounds__(256) void attn_kernel(float* __restrict__ out)
{
    extern __shared__ char sm[];
    const uint32_t sb = smem_u32(sm);
    const int tid  = threadIdx.x;
    const int lane = tid & 31;
    const int wid  = tid >> 5;
    const int wr = wid & 3, wc = wid >> 2;
    const int m0 = wr * 16, n0 = wc * 32;
    const int bb = blockIdx.y;

    const __nv_bfloat16* Khi = g_Khi + (size_t)bb * T_ * HS_;
    const __nv_bfloat16* Klo = g_Klo + (size_t)bb * T_ * HS_;
    const __nv_bfloat16* Qhi = g_Qhi + (size_t)bb * T_ * HS_;
    const __nv_bfloat16* Qlo = g_Qlo + (size_t)bb * T_ * HS_;
    const __nv_bfloat16* Vhi = g_Vhi + (size_t)bb * T_ * HS_;
    const __nv_bfloat16* Vlo = g_Vlo + (size_t)bb * T_ * HS_;

    for (int pass = 0; pass < 2; ++pass) {
        const int ti = pass ? 63 - (int)blockIdx.x : (int)blockIdx.x;
        const int t0 = ti * 64;

        __syncthreads();
        ld_tile(sm, OKHI, Khi + (size_t)t0 * HS_, HS_);
        ld_tile(sm, OKLO, Klo + (size_t)t0 * HS_, HS_);
        ld_tile(sm, OBUF(0) +     0u, Qhi, HS_);
        ld_tile(sm, OBUF(0) +  8192u, Qlo, HS_);
        ld_tile(sm, OBUF(0) + 16384u, Vhi, HS_);
        ld_tile(sm, OBUF(0) + 24576u, Vlo, HS_);

        float Oa[4][4];
#pragma unroll
        for (int j = 0; j < 4; ++j)
#pragma unroll
            for (int q = 0; q < 4; ++q) Oa[j][q] = 0.f;
        float l0 = 0.f, l1 = 0.f;
        const int rr0 = t0 + m0 + (lane >> 2), rr1 = rr0 + 8;

        __syncthreads();

        for (int s0 = 0, it = 0; s0 <= t0; s0 += 64, ++it) {
            const uint32_t cb = OBUF(it & 1);
            const uint32_t nb = OBUF(1 - (it & 1));
            const int sn = s0 + 64;
            const bool hasNext = (sn <= t0);

            uint4 pf[8];
            if (hasNext) {
#pragma unroll
                for (int t4 = 0; t4 < 4; ++t4) {
                    const __nv_bfloat16* s4 =
                        (t4 == 0 ? Qhi : t4 == 1 ? Qlo : t4 == 2 ? Vhi : Vlo)
                        + (size_t)sn * HS_;
#pragma unroll
                    for (int i = 0; i < 2; ++i) {
                        int idx = tid + i * 256, r = idx >> 3, cc = idx & 7;
                        pf[t4*2 + i] = *(const uint4*)(s4 + (size_t)r * HS_ + cc * 8);
                    }
                }
            }

            float S[4][4];
#pragma unroll
            for (int j = 0; j < 4; ++j)
#pragma unroll
                for (int q = 0; q < 4; ++q) S[j][q] = 0.f;
            gemm_split(sb, OKHI, OKLO, cb, cb + 8192u, m0, n0, S);

            if (hasNext) {
#pragma unroll
                for (int t4 = 0; t4 < 4; ++t4) {
                    const uint32_t dst = nb + (uint32_t)t4 * 8192u;
#pragma unroll
                    for (int i = 0; i < 2; ++i) {
                        int idx = tid + i * 256, r = idx >> 3, cc = idx & 7;
                        uint32_t off = (uint32_t)r * 128u
                                     + (uint32_t)((cc ^ (r & 7)) << 4);
                        *(uint4*)(sm + dst + off) = pf[t4*2 + i];
                    }
                }
            }

            const bool diag = (s0 == t0);
#pragma unroll
            for (int j = 0; j < 4; ++j) {
                const int cl = n0 + 8*j + 2*(lane & 3);
                const int cg = s0 + cl;
                float p00 = __expf(S[j][0]);
                float p01 = __expf(S[j][1]);
                float p10 = __expf(S[j][2]);
                float p11 = __expf(S[j][3]);
                if (diag) {
                    if (cg     > rr0) p00 = 0.f;
                    if (cg + 1 > rr0) p01 = 0.f;
                    if (cg     > rr1) p10 = 0.f;
                    if (cg + 1 > rr1) p11 = 0.f;
                }
                l0 += p00 + p01;
                l1 += p10 + p11;
                store_p(sm, m0 + (lane >> 2),     cl, p00, p01);
                store_p(sm, m0 + (lane >> 2) + 8, cl, p10, p11);
            }
            __syncthreads();

            gemm2_split(sb, OPHI, OPLO, cb + 16384u, cb + 24576u, m0, n0, Oa);
            __syncthreads();
        }

        float* l_sm = (float*)(sm + OKHI);
        l0 += __shfl_xor_sync(0xffffffffu, l0, 1);
        l0 += __shfl_xor_sync(0xffffffffu, l0, 2);
        l1 += __shfl_xor_sync(0xffffffffu, l1, 1);
        l1 += __shfl_xor_sync(0xffffffffu, l1, 2);
        if ((lane & 3) == 0) {
            l_sm[wc*64 + m0 + (lane >> 2)]     = l0;
            l_sm[wc*64 + m0 + (lane >> 2) + 8] = l1;
        }
        __syncthreads();
        {
            const int rl = m0 + (lane >> 2);
            const float inv0 = 1.f / (l_sm[rl]     + l_sm[64 + rl]);
            const float inv1 = 1.f / (l_sm[rl + 8] + l_sm[64 + rl + 8]);
            float2* b0p = (float2*)(out + ((size_t)bb * T_ + t0 + rl)     * HS_);
            float2* b1p = (float2*)(out + ((size_t)bb * T_ + t0 + rl + 8) * HS_);
#pragma unroll
            for (int j = 0; j < 4; ++j) {
                const int c = n0 + 8*j + 2*(lane & 3);
                b0p[c >> 1] = make_float2(Oa[j][0]*inv0, Oa[j][1]*inv0);
                b1p[c >> 1] = make_float2(Oa[j][2]*inv1, Oa[j][3]*inv1);
            }
        }
    }
}

// ---------------------------------------------------------------------------
extern "C" void kernel_launch(void* const* d_in, const int* in_sizes, int n_in,
                              void* d_out, int out_size)
{
    (void)in_sizes; (void)n_in; (void)out_size;
    const float* x  = (const float*)d_in[0];
    const float* Wk = (const float*)d_in[1];
    const float* bk = (const float*)d_in[2];
    const float* Wq = (const float*)d_in[3];
    const float* bq = (const float*)d_in[4];
    const float* Wv = (const float*)d_in[5];
    const float* bv = (const float*)d_in[6];
    float* out = (float*)d_out;

    cudaFuncSetAttribute(proj_kernel,
                         cudaFuncAttributeMaxDynamicSharedMemorySize, PROJ_SMEM);
    cudaFuncSetAttribute(attn_kernel,
                         cudaFuncAttributeMaxDynamicSharedMemorySize, ATTN_SMEM);

    wconv_kernel<<<192, 256>>>(Wk, Wq, Wv);
    proj_kernel<<<BT_/128, 256, PROJ_SMEM>>>(x, bk, bq, bv);
    attn_kernel<<<dim3(32, B_), 256, ATTN_SMEM>>>(out);
}